// round 13
// baseline (speedup 1.0000x reference)
#include <cuda_runtime.h>
#include <cstdint>

#define NB   32
#define CINC 64
#define COUTC 128
#define TDIM 256
#define VV   25
#define ICC  32
#define EPSB 1e-5f
#define JD   6400            // t*v columns per (n, channel)

// ---------------- scratch (device globals, no allocation) ----------------
__device__ float g_xT[(size_t)NB*CINC*VV*TDIM];     // tf32 x, [n][c][v][t]
__device__ float g_z[(size_t)NB*256*VV*TDIM];       // z3(0..127), z4(128..255): [n][o'][v][t]
__device__ float g_rT[(size_t)NB*VV*COUTC*TDIM];    // residual + consts, [n][v][o][t]
__device__ float g_hTp[(size_t)NB*VV*COUTC*264];    // padded h rows: [n][u][o][(4+256+4)]
__device__ float g_y[(size_t)NB*VV*COUTC*TDIM];     // final (y+r, relu), [n][u][o][t]
__device__ float g_xbar[NB*CINC*VV];
__device__ float g_p[NB*ICC*VV];
__device__ float g_wstk[384*CINC];                  // [w3*s1; w4*s1; wr*sr], tf32
__device__ float g_b3f[COUTC];
__device__ float g_b4f[COUTC];
__device__ float g_h1[COUTC];
__device__ float g_Cc[COUTC];
__device__ float g_wt2T[1152*COUTC];                // wt*s2 transposed [kk][o], tf32

// ---------------- helpers ----------------
__device__ __forceinline__ float to_tf32(float x) {
    uint32_t r;
    asm("cvt.rna.tf32.f32 %0, %1;" : "=r"(r) : "f"(x));
    return __uint_as_float(r);
}
__device__ __forceinline__ uint32_t smem_u32(const void* p) {
    uint32_t a;
    asm("{ .reg .u64 t; cvta.to.shared.u64 t, %1; cvt.u32.u64 %0, t; }" : "=r"(a) : "l"(p));
    return a;
}

// ---------------- K0: BN folding + weight stack + wt transpose ----------------
__global__ void k_fold(const float* __restrict__ w3, const float* __restrict__ b3,
                       const float* __restrict__ w4, const float* __restrict__ b4,
                       const float* __restrict__ bn1_g, const float* __restrict__ bn1_b,
                       const float* __restrict__ bn1_m, const float* __restrict__ bn1_v,
                       const float* __restrict__ wt,  const float* __restrict__ bt,
                       const float* __restrict__ bn2_g, const float* __restrict__ bn2_b,
                       const float* __restrict__ bn2_m, const float* __restrict__ bn2_v,
                       const float* __restrict__ wr,  const float* __restrict__ br,
                       const float* __restrict__ bnr_g, const float* __restrict__ bnr_b,
                       const float* __restrict__ bnr_m, const float* __restrict__ bnr_v) {
    int idx = blockIdx.x * blockDim.x + threadIdx.x;
    if (idx < COUTC*COUTC*9) {
        int o = idx / 1152, kk = idx - o*1152;
        float s2 = bn2_g[o] * rsqrtf(bn2_v[o] + EPSB);
        g_wt2T[kk*COUTC + o] = to_tf32(wt[idx] * s2);
    }
    if (idx < 384*CINC) {
        int op = idx >> 6, c = idx & 63;
        float w, s;
        if (op < 128) {
            s = bn1_g[op] * rsqrtf(bn1_v[op] + EPSB);
            w = w3[op*CINC + c];
        } else if (op < 256) {
            int o = op - 128;
            s = bn1_g[o] * rsqrtf(bn1_v[o] + EPSB);
            w = w4[o*CINC + c];
        } else {
            int o = op - 256;
            s = bnr_g[o] * rsqrtf(bnr_v[o] + EPSB);
            w = wr[o*CINC + c];
        }
        g_wstk[idx] = to_tf32(w * s);
    }
    if (idx < COUTC) {
        int o = idx;
        float s1 = bn1_g[o] * rsqrtf(bn1_v[o] + EPSB);
        float s2 = bn2_g[o] * rsqrtf(bn2_v[o] + EPSB);
        float sr = bnr_g[o] * rsqrtf(bnr_v[o] + EPSB);
        float h1 = bn1_b[o] - bn1_m[o]*s1;
        float h2 = bn2_b[o] - bn2_m[o]*s2;
        float hr = bnr_b[o] - bnr_m[o]*sr;
        g_b3f[o] = b3[o]*s1;
        g_b4f[o] = b4[o]*s1;
        g_h1[o]  = h1;
        g_Cc[o]  = br[o]*sr + hr + bt[o]*s2 + h2;
    }
}

// ---------------- K0.5: transpose x -> g_xT [n][c][v][t] (tf32) + fused xbar ----------
__global__ void __launch_bounds__(256) k_xT(const float* __restrict__ x) {
    int blk = blockIdx.x;                 // n*64 + c
    __shared__ float s[VV * 257];
    const float* src = x + (size_t)blk * JD;
    int tid = threadIdx.x;
    for (int idx = tid; idx < JD; idx += 256) {
        int t = idx / VV, v = idx - VV*t;
        s[v*257 + t] = src[idx];
    }
    __syncthreads();
    float* dst = g_xT + (size_t)blk * (VV*TDIM);
    #pragma unroll
    for (int v = 0; v < VV; v++) {
        dst[v*TDIM + tid] = to_tf32(s[v*257 + tid]);
    }
    // fused xbar: per-v mean over t (8 lanes per v, shfl reduce)
    {
        int v = tid >> 3, part = tid & 7;
        float sum = 0.f;
        if (v < VV) {
            for (int t = part; t < TDIM; t += 8) sum += s[v*257 + t];
        }
        sum += __shfl_xor_sync(0xffffffffu, sum, 1);
        sum += __shfl_xor_sync(0xffffffffu, sum, 2);
        sum += __shfl_xor_sync(0xffffffffu, sum, 4);
        if (v < VV && part == 0) g_xbar[blk*VV + v] = sum * (1.f / TDIM);
    }
}

// ---------------- K2: p = softmax_v(-(w2.xbar + b2)) ----------------
__global__ void k_p(const float* __restrict__ w2, const float* __restrict__ b2) {
    int blk = blockIdx.x;
    int n = blk / ICC, i = blk % ICC;
    int v = threadIdx.x;
    float val = -1e30f;
    if (v < VV) {
        float acc = b2[i];
        const float* xb = g_xbar + n*CINC*VV;
        #pragma unroll 8
        for (int c = 0; c < CINC; c++) acc += w2[i*CINC + c] * xb[c*VV + v];
        val = -acc;
    }
    float m = val;
    #pragma unroll
    for (int s = 16; s; s >>= 1) m = fmaxf(m, __shfl_xor_sync(0xffffffffu, m, s));
    float e = (v < VV) ? expf(val - m) : 0.f;
    float ssum = e;
    #pragma unroll
    for (int s = 16; s; s >>= 1) ssum += __shfl_xor_sync(0xffffffffu, ssum, s);
    if (v < VV) g_p[blk*VV + v] = e / ssum;
}

// ---------------- K3: Z = Wstack(384x64) @ xT(64 x [v][t]) per n, tf32 mma ----------
#define ZPA 68     // [o][k]: banks 4g+tg distinct
#define ZPB 136    // [k][t]: banks 8tg+g distinct

__global__ void __launch_bounds__(256, 2) k_zgemm() {
    __shared__ float sA[128*ZPA];
    __shared__ float sB[64*ZPB];
    __shared__ float ccs[COUTC];
    int tid = threadIdx.x, wid = tid >> 5, lane = tid & 31;
    int g = lane >> 2, tg = lane & 3;
    int warp_m = wid & 3, warp_n = wid >> 2;
    int jb = blockIdx.x;                 // 0..49
    int v  = jb >> 1, t0 = (jb & 1) * 128;
    int mg = blockIdx.y;                 // 0:z3 1:z4 2:zr
    int m0 = mg * 128;
    int n  = blockIdx.z;

    #pragma unroll
    for (int e = 0; e < 8; e++) {
        int i4 = e*256 + tid;
        int o = i4 >> 4, k4 = (i4 & 15) * 4;
        *(float4*)&sA[o*ZPA + k4] = *(const float4*)&g_wstk[(m0 + o)*CINC + k4];
    }
    #pragma unroll
    for (int e = 0; e < 8; e++) {
        int i4 = e*256 + tid;
        int c = i4 >> 5, t4 = (i4 & 31) * 4;
        *(float4*)&sB[c*ZPB + t4] =
            *(const float4*)&g_xT[(((size_t)n*CINC + c)*VV + v)*TDIM + t0 + t4];
    }
    if (mg == 2 && tid < COUTC) ccs[tid] = g_Cc[tid];
    __syncthreads();

    float acc[2][8][4];
    #pragma unroll
    for (int mt = 0; mt < 2; mt++)
        #pragma unroll
        for (int nt = 0; nt < 8; nt++)
            #pragma unroll
            for (int q = 0; q < 4; q++) acc[mt][nt][q] = 0.f;

    #pragma unroll
    for (int ks = 0; ks < 8; ks++) {
        int k0 = ks*8;
        uint32_t a[2][4];
        #pragma unroll
        for (int mt = 0; mt < 2; mt++) {
            int ob = warp_m*32 + mt*16;
            a[mt][0] = __float_as_uint(sA[(ob + g    )*ZPA + k0 + tg    ]);
            a[mt][1] = __float_as_uint(sA[(ob + g + 8)*ZPA + k0 + tg    ]);
            a[mt][2] = __float_as_uint(sA[(ob + g    )*ZPA + k0 + tg + 4]);
            a[mt][3] = __float_as_uint(sA[(ob + g + 8)*ZPA + k0 + tg + 4]);
        }
        #pragma unroll
        for (int nt = 0; nt < 8; nt++) {
            int tb = warp_n*64 + nt*8;
            uint32_t b0 = __float_as_uint(sB[(k0 + tg    )*ZPB + tb + g]);
            uint32_t b1 = __float_as_uint(sB[(k0 + tg + 4)*ZPB + tb + g]);
            #pragma unroll
            for (int mt = 0; mt < 2; mt++) {
                asm volatile(
                    "mma.sync.aligned.m16n8k8.row.col.f32.tf32.tf32.f32 "
                    "{%0,%1,%2,%3}, {%4,%5,%6,%7}, {%8,%9}, {%0,%1,%2,%3};"
                    : "+f"(acc[mt][nt][0]), "+f"(acc[mt][nt][1]),
                      "+f"(acc[mt][nt][2]), "+f"(acc[mt][nt][3])
                    : "r"(a[mt][0]), "r"(a[mt][1]), "r"(a[mt][2]), "r"(a[mt][3]),
                      "r"(b0), "r"(b1));
            }
        }
    }

    if (mg < 2) {
        size_t zb = (size_t)n*(256*JD) + (size_t)m0*JD + (size_t)v*TDIM + t0;
        #pragma unroll
        for (int mt = 0; mt < 2; mt++) {
            int ob = warp_m*32 + mt*16;
            #pragma unroll
            for (int nt = 0; nt < 8; nt++) {
                int tl = warp_n*64 + nt*8 + 2*tg;
                *(float2*)&g_z[zb + (size_t)(ob + g    )*JD + tl] =
                    make_float2(acc[mt][nt][0], acc[mt][nt][1]);
                *(float2*)&g_z[zb + (size_t)(ob + g + 8)*JD + tl] =
                    make_float2(acc[mt][nt][2], acc[mt][nt][3]);
            }
        }
    } else {
        size_t rb = (((size_t)n*VV + v)*COUTC)*TDIM + t0;
        #pragma unroll
        for (int mt = 0; mt < 2; mt++) {
            int ob = warp_m*32 + mt*16;
            #pragma unroll
            for (int nt = 0; nt < 8; nt++) {
                int tl = warp_n*64 + nt*8 + 2*tg;
                float c0 = ccs[ob + g], c1 = ccs[ob + g + 8];
                *(float2*)&g_rT[rb + (size_t)(ob + g    )*TDIM + tl] =
                    make_float2(acc[mt][nt][0] + c0, acc[mt][nt][1] + c0);
                *(float2*)&g_rT[rb + (size_t)(ob + g + 8)*TDIM + tl] =
                    make_float2(acc[mt][nt][2] + c1, acc[mt][nt][3] + c1);
            }
        }
    }
}

// ---------------- K3.5: p-dot + A-mix + BN1/ReLU -> g_hTp (padded rows) ----------
__global__ void __launch_bounds__(256) k_amix(const float* __restrict__ A) {
    int blk = blockIdx.x;                 // n*128 + o
    int n = blk >> 7, o = blk & 127;
    __shared__ float As[VV*VV];
    __shared__ float ps[VV];
    int tid = threadIdx.x;                // = t

    for (int idx = tid; idx < VV*VV; idx += 256) As[idx] = A[idx];
    if (tid < VV) ps[tid] = g_p[(n*ICC + (o & 31))*VV + tid];
    __syncthreads();

    const float* z3p = g_z + (size_t)n*(256*JD) + (size_t)o*JD;
    const float* z4p = z3p + (size_t)128*JD;
    float b4 = g_b4f[o];
    float base = g_b3f[o] + g_h1[o];
    float z4r[VV];
    #pragma unroll
    for (int v = 0; v < VV; v++) {
        base += ps[v] * z3p[v*TDIM + tid];
        z4r[v] = z4p[v*TDIM + tid] + b4;
    }

    size_t hb = ((size_t)(n*VV)*COUTC + o)*264;     // + u*(128*264)
    #pragma unroll 1
    for (int u = 0; u < VV; u++) {
        float acc = base;
        const float* Ar = &As[u*VV];
        #pragma unroll
        for (int v = 0; v < VV; v++) acc += Ar[v] * z4r[v];
        size_t row = hb + (size_t)u*(COUTC*264);
        g_hTp[row + 4 + tid] = to_tf32(fmaxf(acc, 0.f));
        if (tid < 4) { g_hTp[row + tid] = 0.f; g_hTp[row + 260 + tid] = 0.f; }
    }
}

// ---------------- K4: temporal conv GEMM, full t=256 per block, 512 threads ----------
#define NCH 144
#define MPA 136          // A [j][o] pitch
#define ASTG (8*MPA)     // 1088 floats per A stage
#define SH_OFF (4*ASTG)  // 4352
#define SHP 264          // ring row = full padded h row
#define SMEM_FL (COUTC*68)  // 8704 floats: epilogue stage dominates

__global__ void __launch_bounds__(512) k_mma() {
    __shared__ float sm[SMEM_FL];
    int tid = threadIdx.x, wid = tid >> 5, lane = tid & 31;
    int g = lane >> 2, tg = lane & 3;
    int warp_m = wid & 3, warp_n = wid >> 2;   // 4m x 4n, warp tile 32o x 64t
    int u = blockIdx.x;
    int n = blockIdx.y;
    uint32_t sb = smem_u32(sm);
    const float* hrow = g_hTp + ((size_t)(n*VV + u)*COUTC)*264;   // + i*264

    float acc[2][8][4];
    #pragma unroll
    for (int mt = 0; mt < 2; mt++)
        #pragma unroll
        for (int nt = 0; nt < 8; nt++)
            #pragma unroll
            for (int q = 0; q < 4; q++) acc[mt][nt][q] = 0.f;

    int next_row = 0;
    auto issue = [&](int c) {
        if (tid < 256) {   // A chunk c -> stage c&3
            int j = tid >> 5, o4 = (tid & 31) * 4;
            uint32_t dst = sb + (((c & 3)*ASTG) + j*MPA + o4) * 4;
            const float* src = g_wt2T + (size_t)(c*8 + j)*COUTC + o4;
            asm volatile("cp.async.ca.shared.global [%0], [%1], 16;" :: "r"(dst), "l"(src));
        }
        int imax = (8*c + 7) / 9;
        while (next_row <= imax) {
            if (tid < 66) {
                int slot = next_row % 6;
                uint32_t dst = sb + (SH_OFF + slot*SHP + tid*4) * 4;
                const float* src = hrow + (size_t)next_row*264 + tid*4;
                asm volatile("cp.async.ca.shared.global [%0], [%1], 16;" :: "r"(dst), "l"(src));
            }
            next_row++;
        }
        asm volatile("cp.async.commit_group;" ::: "memory");
    };

    issue(0); issue(1); issue(2);
    for (int c = 0; c < NCH; c++) {
        asm volatile("cp.async.wait_group 2;" ::: "memory");
        __syncthreads();
        if (c + 3 < NCH) issue(c + 3);
        else asm volatile("cp.async.commit_group;" ::: "memory");

        const float* sA = sm + (c & 3)*ASTG;
        uint32_t a[2][4];
        #pragma unroll
        for (int mt = 0; mt < 2; mt++) {
            int ob = warp_m*32 + mt*16;
            a[mt][0] = __float_as_uint(sA[ tg     *MPA + ob + g    ]);
            a[mt][1] = __float_as_uint(sA[ tg     *MPA + ob + g + 8]);
            a[mt][2] = __float_as_uint(sA[(tg + 4)*MPA + ob + g    ]);
            a[mt][3] = __float_as_uint(sA[(tg + 4)*MPA + ob + g + 8]);
        }
        int kb0 = c*8 + tg, kb1 = kb0 + 4;
        int i0 = (kb0 * 7282) >> 16; int k0 = kb0 - 9*i0;
        int i1 = (kb1 * 7282) >> 16; int k1 = kb1 - 9*i1;
        const float* h0 = sm + SH_OFF + (i0 % 6)*SHP + k0 + g;
        const float* h1 = sm + SH_OFF + (i1 % 6)*SHP + k1 + g;
        #pragma unroll
        for (int nt = 0; nt < 8; nt++) {
            int tb = warp_n*64 + nt*8;
            uint32_t b0 = __float_as_uint(h0[tb]);
            uint32_t b1 = __float_as_uint(h1[tb]);
            #pragma unroll
            for (int mt = 0; mt < 2; mt++) {
                asm volatile(
                    "mma.sync.aligned.m16n8k8.row.col.f32.tf32.tf32.f32 "
                    "{%0,%1,%2,%3}, {%4,%5,%6,%7}, {%8,%9}, {%0,%1,%2,%3};"
                    : "+f"(acc[mt][nt][0]), "+f"(acc[mt][nt][1]),
                      "+f"(acc[mt][nt][2]), "+f"(acc[mt][nt][3])
                    : "r"(a[mt][0]), "r"(a[mt][1]), "r"(a[mt][2]), "r"(a[mt][3]),
                      "r"(b0), "r"(b1));
            }
        }
    }

    // Epilogue: 4 rounds of 64 t; acc -> stage -> (+rT, ReLU) -> g_y (float4)
    float* stage = sm;
    size_t yb = (((size_t)n*VV + u)*COUTC)*TDIM;
    #pragma unroll
    for (int rr = 0; rr < 4; rr++) {
        __syncthreads();
        if (warp_n == rr) {
            #pragma unroll
            for (int mt = 0; mt < 2; mt++) {
                int o = warp_m*32 + mt*16 + g;
                #pragma unroll
                for (int nt = 0; nt < 8; nt++) {
                    int tl = nt*8 + 2*tg;
                    stage[ o     *68 + tl    ] = acc[mt][nt][0];
                    stage[ o     *68 + tl + 1] = acc[mt][nt][1];
                    stage[(o + 8)*68 + tl    ] = acc[mt][nt][2];
                    stage[(o + 8)*68 + tl + 1] = acc[mt][nt][3];
                }
            }
        }
        __syncthreads();
        #pragma unroll
        for (int e = 0; e < 4; e++) {
            int i4 = e*512 + tid;            // 2048 float4 = 128 o x 64 t
            int o = i4 >> 4, tl = (i4 & 15) * 4;
            size_t gi = yb + (size_t)o*TDIM + rr*64 + tl;
            float4 sv = *(float4*)&stage[o*68 + tl];
            float4 rv = *(const float4*)&g_rT[gi];
            sv.x = fmaxf(sv.x + rv.x, 0.f);
            sv.y = fmaxf(sv.y + rv.y, 0.f);
            sv.z = fmaxf(sv.z + rv.z, 0.f);
            sv.w = fmaxf(sv.w + rv.w, 0.f);
            *(float4*)&g_y[gi] = sv;
        }
    }
}

// ---------------- K5: pure transpose g_y -> out [n][o][t][u] ----------------
__global__ void __launch_bounds__(256) k_out(float* __restrict__ out) {
    int blk = blockIdx.x;                  // n*128 + o
    int n = blk >> 7, o = blk & 127;
    __shared__ float sy[TDIM * 27];
    int tid = threadIdx.x;
    size_t ybase = (((size_t)n*VV)*COUTC + o)*TDIM;
    #pragma unroll
    for (int u = 0; u < VV; u++) {
        sy[tid*27 + u] = g_y[ybase + (size_t)u*COUTC*TDIM + tid];
    }
    __syncthreads();
    size_t ob = ((size_t)n*COUTC + o) * (size_t)JD;
    for (int idx = tid; idx < JD; idx += 256) {
        int t = idx / VV, u = idx - VV*t;
        out[ob + idx] = sy[t*27 + u];
    }
}

// ---------------- launch ----------------
extern "C" void kernel_launch(void* const* d_in, const int* in_sizes, int n_in,
                              void* d_out, int out_size) {
    const float* x     = (const float*)d_in[0];
    const float* A     = (const float*)d_in[1];
    const float* w2    = (const float*)d_in[4];
    const float* b2    = (const float*)d_in[5];
    const float* w3    = (const float*)d_in[6];
    const float* b3    = (const float*)d_in[7];
    const float* w4    = (const float*)d_in[8];
    const float* b4    = (const float*)d_in[9];
    const float* bn1_g = (const float*)d_in[10];
    const float* bn1_b = (const float*)d_in[11];
    const float* bn1_m = (const float*)d_in[12];
    const float* bn1_v = (const float*)d_in[13];
    const float* wt    = (const float*)d_in[14];
    const float* bt    = (const float*)d_in[15];
    const float* bn2_g = (const float*)d_in[16];
    const float* bn2_b = (const float*)d_in[17];
    const float* bn2_m = (const float*)d_in[18];
    const float* bn2_v = (const float*)d_in[19];
    const float* wr    = (const float*)d_in[20];
    const float* br    = (const float*)d_in[21];
    const float* bnr_g = (const float*)d_in[22];
    const float* bnr_b = (const float*)d_in[23];
    const float* bnr_m = (const float*)d_in[24];
    const float* bnr_v = (const float*)d_in[25];
    float* out = (float*)d_out;

    k_fold<<<(COUTC*COUTC*9 + 255)/256, 256>>>(w3, b3, w4, b4,
                                               bn1_g, bn1_b, bn1_m, bn1_v,
                                               wt, bt, bn2_g, bn2_b, bn2_m, bn2_v,
                                               wr, br, bnr_g, bnr_b, bnr_m, bnr_v);
    k_xT<<<NB*CINC, 256>>>(x);
    k_p<<<NB*ICC, 32>>>(w2, b2);
    k_zgemm<<<dim3(50, 3, NB), 256>>>();
    k_amix<<<NB*COUTC, 256>>>(A);
    k_mma<<<dim3(VV, NB), 512>>>();
    k_out<<<NB*COUTC, 256>>>(out);
}

// round 14
// speedup vs baseline: 1.2405x; 1.2405x over previous
#include <cuda_runtime.h>
#include <cstdint>

#define NB   32
#define CINC 64
#define COUTC 128
#define TDIM 256
#define VV   25
#define ICC  32
#define EPSB 1e-5f
#define JD   6400            // t*v columns per (n, channel)

// ---------------- scratch (device globals, no allocation) ----------------
__device__ float g_xT[(size_t)NB*CINC*VV*TDIM];     // tf32 x, [n][c][v][t]
__device__ float g_z[(size_t)NB*256*VV*TDIM];       // z3(0..127), z4(128..255): [n][o'][v][t]
__device__ float g_rT[(size_t)NB*VV*COUTC*TDIM];    // residual + consts, [n][v][o][t]
__device__ float g_hTp[(size_t)NB*VV*COUTC*264];    // padded h rows: [n][u][o][(4+256+4)]
__device__ float g_y[(size_t)NB*VV*COUTC*TDIM];     // final (y+r, relu), [n][u][o][t]
__device__ float g_xbar[NB*CINC*VV];
__device__ float g_p[NB*ICC*VV];
__device__ float g_wstk[384*CINC];                  // [w3*s1; w4*s1; wr*sr], tf32
__device__ float g_b3f[COUTC];
__device__ float g_b4f[COUTC];
__device__ float g_h1[COUTC];
__device__ float g_Cc[COUTC];
__device__ float g_wt2T[1152*COUTC];                // wt*s2 transposed [kk][o], tf32

// ---------------- helpers ----------------
__device__ __forceinline__ float to_tf32(float x) {
    uint32_t r;
    asm("cvt.rna.tf32.f32 %0, %1;" : "=r"(r) : "f"(x));
    return __uint_as_float(r);
}
__device__ __forceinline__ uint32_t smem_u32(const void* p) {
    uint32_t a;
    asm("{ .reg .u64 t; cvta.to.shared.u64 t, %1; cvt.u32.u64 %0, t; }" : "=r"(a) : "l"(p));
    return a;
}

// ---------------- K0: BN folding + weight stack + wt transpose ----------------
__global__ void k_fold(const float* __restrict__ w3, const float* __restrict__ b3,
                       const float* __restrict__ w4, const float* __restrict__ b4,
                       const float* __restrict__ bn1_g, const float* __restrict__ bn1_b,
                       const float* __restrict__ bn1_m, const float* __restrict__ bn1_v,
                       const float* __restrict__ wt,  const float* __restrict__ bt,
                       const float* __restrict__ bn2_g, const float* __restrict__ bn2_b,
                       const float* __restrict__ bn2_m, const float* __restrict__ bn2_v,
                       const float* __restrict__ wr,  const float* __restrict__ br,
                       const float* __restrict__ bnr_g, const float* __restrict__ bnr_b,
                       const float* __restrict__ bnr_m, const float* __restrict__ bnr_v) {
    int idx = blockIdx.x * blockDim.x + threadIdx.x;
    if (idx < COUTC*COUTC*9) {
        int o = idx / 1152, kk = idx - o*1152;
        float s2 = bn2_g[o] * rsqrtf(bn2_v[o] + EPSB);
        g_wt2T[kk*COUTC + o] = to_tf32(wt[idx] * s2);
    }
    if (idx < 384*CINC) {
        int op = idx >> 6, c = idx & 63;
        float w, s;
        if (op < 128) {
            s = bn1_g[op] * rsqrtf(bn1_v[op] + EPSB);
            w = w3[op*CINC + c];
        } else if (op < 256) {
            int o = op - 128;
            s = bn1_g[o] * rsqrtf(bn1_v[o] + EPSB);
            w = w4[o*CINC + c];
        } else {
            int o = op - 256;
            s = bnr_g[o] * rsqrtf(bnr_v[o] + EPSB);
            w = wr[o*CINC + c];
        }
        g_wstk[idx] = to_tf32(w * s);
    }
    if (idx < COUTC) {
        int o = idx;
        float s1 = bn1_g[o] * rsqrtf(bn1_v[o] + EPSB);
        float s2 = bn2_g[o] * rsqrtf(bn2_v[o] + EPSB);
        float sr = bnr_g[o] * rsqrtf(bnr_v[o] + EPSB);
        float h1 = bn1_b[o] - bn1_m[o]*s1;
        float h2 = bn2_b[o] - bn2_m[o]*s2;
        float hr = bnr_b[o] - bnr_m[o]*sr;
        g_b3f[o] = b3[o]*s1;
        g_b4f[o] = b4[o]*s1;
        g_h1[o]  = h1;
        g_Cc[o]  = br[o]*sr + hr + bt[o]*s2 + h2;
    }
}

// ---------------- K0.5: transpose x -> g_xT [n][c][v][t] (tf32) + fused xbar ----------
__global__ void __launch_bounds__(256) k_xT(const float* __restrict__ x) {
    int blk = blockIdx.x;                 // n*64 + c
    __shared__ float s[VV * 257];
    const float* src = x + (size_t)blk * JD;
    int tid = threadIdx.x;
    for (int idx = tid; idx < JD; idx += 256) {
        int t = idx / VV, v = idx - VV*t;
        s[v*257 + t] = src[idx];
    }
    __syncthreads();
    float* dst = g_xT + (size_t)blk * (VV*TDIM);
    #pragma unroll
    for (int v = 0; v < VV; v++) {
        dst[v*TDIM + tid] = to_tf32(s[v*257 + tid]);
    }
    // fused xbar: per-v mean over t (8 lanes per v, shfl reduce)
    {
        int v = tid >> 3, part = tid & 7;
        float sum = 0.f;
        if (v < VV) {
            for (int t = part; t < TDIM; t += 8) sum += s[v*257 + t];
        }
        sum += __shfl_xor_sync(0xffffffffu, sum, 1);
        sum += __shfl_xor_sync(0xffffffffu, sum, 2);
        sum += __shfl_xor_sync(0xffffffffu, sum, 4);
        if (v < VV && part == 0) g_xbar[blk*VV + v] = sum * (1.f / TDIM);
    }
}

// ---------------- K2: p = softmax_v(-(w2.xbar + b2)) ----------------
__global__ void k_p(const float* __restrict__ w2, const float* __restrict__ b2) {
    int blk = blockIdx.x;
    int n = blk / ICC, i = blk % ICC;
    int v = threadIdx.x;
    float val = -1e30f;
    if (v < VV) {
        float acc = b2[i];
        const float* xb = g_xbar + n*CINC*VV;
        #pragma unroll 8
        for (int c = 0; c < CINC; c++) acc += w2[i*CINC + c] * xb[c*VV + v];
        val = -acc;
    }
    float m = val;
    #pragma unroll
    for (int s = 16; s; s >>= 1) m = fmaxf(m, __shfl_xor_sync(0xffffffffu, m, s));
    float e = (v < VV) ? expf(val - m) : 0.f;
    float ssum = e;
    #pragma unroll
    for (int s = 16; s; s >>= 1) ssum += __shfl_xor_sync(0xffffffffu, ssum, s);
    if (v < VV) g_p[blk*VV + v] = e / ssum;
}

// ---------------- K3: Z = Wstack(384x64) @ xT(64 x [v][t]) per n, tf32 mma ----------
#define ZPA 68     // [o][k]: banks 4g+tg distinct
#define ZPB 136    // [k][t]: banks 8tg+g distinct

__global__ void __launch_bounds__(256, 2) k_zgemm() {
    __shared__ float sA[128*ZPA];
    __shared__ float sB[64*ZPB];
    __shared__ float ccs[COUTC];
    int tid = threadIdx.x, wid = tid >> 5, lane = tid & 31;
    int g = lane >> 2, tg = lane & 3;
    int warp_m = wid & 3, warp_n = wid >> 2;
    int jb = blockIdx.x;                 // 0..49
    int v  = jb >> 1, t0 = (jb & 1) * 128;
    int mg = blockIdx.y;                 // 0:z3 1:z4 2:zr
    int m0 = mg * 128;
    int n  = blockIdx.z;

    #pragma unroll
    for (int e = 0; e < 8; e++) {
        int i4 = e*256 + tid;
        int o = i4 >> 4, k4 = (i4 & 15) * 4;
        *(float4*)&sA[o*ZPA + k4] = *(const float4*)&g_wstk[(m0 + o)*CINC + k4];
    }
    #pragma unroll
    for (int e = 0; e < 8; e++) {
        int i4 = e*256 + tid;
        int c = i4 >> 5, t4 = (i4 & 31) * 4;
        *(float4*)&sB[c*ZPB + t4] =
            *(const float4*)&g_xT[(((size_t)n*CINC + c)*VV + v)*TDIM + t0 + t4];
    }
    if (mg == 2 && tid < COUTC) ccs[tid] = g_Cc[tid];
    __syncthreads();

    float acc[2][8][4];
    #pragma unroll
    for (int mt = 0; mt < 2; mt++)
        #pragma unroll
        for (int nt = 0; nt < 8; nt++)
            #pragma unroll
            for (int q = 0; q < 4; q++) acc[mt][nt][q] = 0.f;

    #pragma unroll
    for (int ks = 0; ks < 8; ks++) {
        int k0 = ks*8;
        uint32_t a[2][4];
        #pragma unroll
        for (int mt = 0; mt < 2; mt++) {
            int ob = warp_m*32 + mt*16;
            a[mt][0] = __float_as_uint(sA[(ob + g    )*ZPA + k0 + tg    ]);
            a[mt][1] = __float_as_uint(sA[(ob + g + 8)*ZPA + k0 + tg    ]);
            a[mt][2] = __float_as_uint(sA[(ob + g    )*ZPA + k0 + tg + 4]);
            a[mt][3] = __float_as_uint(sA[(ob + g + 8)*ZPA + k0 + tg + 4]);
        }
        #pragma unroll
        for (int nt = 0; nt < 8; nt++) {
            int tb = warp_n*64 + nt*8;
            uint32_t b0 = __float_as_uint(sB[(k0 + tg    )*ZPB + tb + g]);
            uint32_t b1 = __float_as_uint(sB[(k0 + tg + 4)*ZPB + tb + g]);
            #pragma unroll
            for (int mt = 0; mt < 2; mt++) {
                asm volatile(
                    "mma.sync.aligned.m16n8k8.row.col.f32.tf32.tf32.f32 "
                    "{%0,%1,%2,%3}, {%4,%5,%6,%7}, {%8,%9}, {%0,%1,%2,%3};"
                    : "+f"(acc[mt][nt][0]), "+f"(acc[mt][nt][1]),
                      "+f"(acc[mt][nt][2]), "+f"(acc[mt][nt][3])
                    : "r"(a[mt][0]), "r"(a[mt][1]), "r"(a[mt][2]), "r"(a[mt][3]),
                      "r"(b0), "r"(b1));
            }
        }
    }

    if (mg < 2) {
        size_t zb = (size_t)n*(256*JD) + (size_t)m0*JD + (size_t)v*TDIM + t0;
        #pragma unroll
        for (int mt = 0; mt < 2; mt++) {
            int ob = warp_m*32 + mt*16;
            #pragma unroll
            for (int nt = 0; nt < 8; nt++) {
                int tl = warp_n*64 + nt*8 + 2*tg;
                *(float2*)&g_z[zb + (size_t)(ob + g    )*JD + tl] =
                    make_float2(acc[mt][nt][0], acc[mt][nt][1]);
                *(float2*)&g_z[zb + (size_t)(ob + g + 8)*JD + tl] =
                    make_float2(acc[mt][nt][2], acc[mt][nt][3]);
            }
        }
    } else {
        size_t rb = (((size_t)n*VV + v)*COUTC)*TDIM + t0;
        #pragma unroll
        for (int mt = 0; mt < 2; mt++) {
            int ob = warp_m*32 + mt*16;
            #pragma unroll
            for (int nt = 0; nt < 8; nt++) {
                int tl = warp_n*64 + nt*8 + 2*tg;
                float c0 = ccs[ob + g], c1 = ccs[ob + g + 8];
                *(float2*)&g_rT[rb + (size_t)(ob + g    )*TDIM + tl] =
                    make_float2(acc[mt][nt][0] + c0, acc[mt][nt][1] + c0);
                *(float2*)&g_rT[rb + (size_t)(ob + g + 8)*TDIM + tl] =
                    make_float2(acc[mt][nt][2] + c1, acc[mt][nt][3] + c1);
            }
        }
    }
}

// ---------------- K3.5: p-dot + A-mix + BN1/ReLU -> g_hTp (padded rows) ----------
__global__ void __launch_bounds__(256) k_amix(const float* __restrict__ A) {
    int blk = blockIdx.x;                 // n*128 + o
    int n = blk >> 7, o = blk & 127;
    __shared__ float As[VV*VV];
    __shared__ float ps[VV];
    int tid = threadIdx.x;                // = t

    for (int idx = tid; idx < VV*VV; idx += 256) As[idx] = A[idx];
    if (tid < VV) ps[tid] = g_p[(n*ICC + (o & 31))*VV + tid];
    __syncthreads();

    const float* z3p = g_z + (size_t)n*(256*JD) + (size_t)o*JD;
    const float* z4p = z3p + (size_t)128*JD;
    float b4 = g_b4f[o];
    float base = g_b3f[o] + g_h1[o];
    float z4r[VV];
    #pragma unroll
    for (int v = 0; v < VV; v++) {
        base += ps[v] * z3p[v*TDIM + tid];
        z4r[v] = z4p[v*TDIM + tid] + b4;
    }

    size_t hb = ((size_t)(n*VV)*COUTC + o)*264;     // + u*(128*264)
    #pragma unroll 1
    for (int u = 0; u < VV; u++) {
        float acc = base;
        const float* Ar = &As[u*VV];
        #pragma unroll
        for (int v = 0; v < VV; v++) acc += Ar[v] * z4r[v];
        size_t row = hb + (size_t)u*(COUTC*264);
        g_hTp[row + 4 + tid] = to_tf32(fmaxf(acc, 0.f));
        if (tid < 4) { g_hTp[row + tid] = 0.f; g_hTp[row + 260 + tid] = 0.f; }
    }
}

// ---------------- K4: temporal conv GEMM, KC=8, 4-stage A + 6-row H ring ----------
#define NCH 144
#define MPA 136        // A [j][o] pitch: banks 8tg+g distinct
#define ASTG (8*MPA)   // 1088 floats per A stage
#define SH_OFF (4*ASTG)  // 4352
#define SHP 264        // ring row pitch (136 used)
#define SMEM_FL (COUTC*68)  // 8704: epilogue stage dominates

__global__ void __launch_bounds__(256, 2) k_mma() {
    __shared__ float sm[SMEM_FL];
    int tid = threadIdx.x, wid = tid >> 5, lane = tid & 31;
    int g = lane >> 2, tg = lane & 3;
    int warp_m = wid & 3, warp_n = wid >> 2;
    int t0 = blockIdx.x * 128;
    int u  = blockIdx.y;
    int n  = blockIdx.z;
    uint32_t sb = smem_u32(sm);
    const float* hrow = g_hTp + ((size_t)(n*VV + u)*COUTC)*264;   // + i*264 (+t0)

    float acc[2][8][4];
    #pragma unroll
    for (int mt = 0; mt < 2; mt++)
        #pragma unroll
        for (int nt = 0; nt < 8; nt++)
            #pragma unroll
            for (int q = 0; q < 4; q++) acc[mt][nt][q] = 0.f;

    int next_row = 0;
    auto issue = [&](int c) {
        {   // A chunk c -> stage c&3 : one 16B cp.async per thread
            int j = tid >> 5, o4 = (tid & 31) * 4;
            uint32_t dst = sb + (((c & 3)*ASTG) + j*MPA + o4) * 4;
            const float* src = g_wt2T + (size_t)(c*8 + j)*COUTC + o4;
            asm volatile("cp.async.ca.shared.global [%0], [%1], 16;" :: "r"(dst), "l"(src));
        }
        int imax = (8*c + 7) / 9;
        while (next_row <= imax) {
            if (tid < 34) {
                int slot = next_row % 6;
                uint32_t dst = sb + (SH_OFF + slot*SHP + tid*4) * 4;
                const float* src = hrow + (size_t)next_row*264 + t0 + tid*4;
                asm volatile("cp.async.ca.shared.global [%0], [%1], 16;" :: "r"(dst), "l"(src));
            }
            next_row++;
        }
        asm volatile("cp.async.commit_group;" ::: "memory");
    };

    issue(0); issue(1); issue(2);
    for (int c = 0; c < NCH; c++) {
        asm volatile("cp.async.wait_group 2;" ::: "memory");
        __syncthreads();
        if (c + 3 < NCH) issue(c + 3);
        else asm volatile("cp.async.commit_group;" ::: "memory");

        const float* sA = sm + (c & 3)*ASTG;
        uint32_t a[2][4];
        #pragma unroll
        for (int mt = 0; mt < 2; mt++) {
            int ob = warp_m*32 + mt*16;
            a[mt][0] = __float_as_uint(sA[ tg     *MPA + ob + g    ]);
            a[mt][1] = __float_as_uint(sA[ tg     *MPA + ob + g + 8]);
            a[mt][2] = __float_as_uint(sA[(tg + 4)*MPA + ob + g    ]);
            a[mt][3] = __float_as_uint(sA[(tg + 4)*MPA + ob + g + 8]);
        }
        int kb0 = c*8 + tg, kb1 = kb0 + 4;
        int i0 = (kb0 * 7282) >> 16; int k0 = kb0 - 9*i0;
        int i1 = (kb1 * 7282) >> 16; int k1 = kb1 - 9*i1;
        const float* h0 = sm + SH_OFF + (i0 % 6)*SHP + k0 + g;
        const float* h1 = sm + SH_OFF + (i1 % 6)*SHP + k1 + g;
        #pragma unroll
        for (int nt = 0; nt < 8; nt++) {
            int tb = warp_n*64 + nt*8;
            uint32_t b0 = __float_as_uint(h0[tb]);
            uint32_t b1 = __float_as_uint(h1[tb]);
            #pragma unroll
            for (int mt = 0; mt < 2; mt++) {
                asm volatile(
                    "mma.sync.aligned.m16n8k8.row.col.f32.tf32.tf32.f32 "
                    "{%0,%1,%2,%3}, {%4,%5,%6,%7}, {%8,%9}, {%0,%1,%2,%3};"
                    : "+f"(acc[mt][nt][0]), "+f"(acc[mt][nt][1]),
                      "+f"(acc[mt][nt][2]), "+f"(acc[mt][nt][3])
                    : "r"(a[mt][0]), "r"(a[mt][1]), "r"(a[mt][2]), "r"(a[mt][3]),
                      "r"(b0), "r"(b1));
            }
        }
    }

    // Epilogue: acc -> stage -> (+rT, ReLU) -> g_y, float4
    float* stage = sm;
    size_t yb = (((size_t)n*VV + u)*COUTC)*TDIM + t0;
    #pragma unroll
    for (int rr = 0; rr < 2; rr++) {
        __syncthreads();
        if (warp_n == rr) {
            #pragma unroll
            for (int mt = 0; mt < 2; mt++) {
                int o = warp_m*32 + mt*16 + g;
                #pragma unroll
                for (int nt = 0; nt < 8; nt++) {
                    int tl = nt*8 + 2*tg;
                    stage[ o     *68 + tl    ] = acc[mt][nt][0];
                    stage[ o     *68 + tl + 1] = acc[mt][nt][1];
                    stage[(o + 8)*68 + tl    ] = acc[mt][nt][2];
                    stage[(o + 8)*68 + tl + 1] = acc[mt][nt][3];
                }
            }
        }
        __syncthreads();
        #pragma unroll
        for (int e = 0; e < 8; e++) {
            int i4 = e*256 + tid;            // 2048 float4 = 128 o x 64 t
            int o = i4 >> 4, tl = (i4 & 15) * 4;
            size_t gi = yb + (size_t)o*TDIM + rr*64 + tl;
            float4 sv = *(float4*)&stage[o*68 + tl];
            float4 rv = *(const float4*)&g_rT[gi];
            sv.x = fmaxf(sv.x + rv.x, 0.f);
            sv.y = fmaxf(sv.y + rv.y, 0.f);
            sv.z = fmaxf(sv.z + rv.z, 0.f);
            sv.w = fmaxf(sv.w + rv.w, 0.f);
            *(float4*)&g_y[gi] = sv;
        }
    }
}

// ---------------- K5: pure transpose g_y -> out [n][o][t][u] ----------------
__global__ void __launch_bounds__(256) k_out(float* __restrict__ out) {
    int blk = blockIdx.x;                  // n*128 + o
    int n = blk >> 7, o = blk & 127;
    __shared__ float sy[TDIM * 27];
    int tid = threadIdx.x;
    size_t ybase = (((size_t)n*VV)*COUTC + o)*TDIM;
    #pragma unroll
    for (int u = 0; u < VV; u++) {
        sy[tid*27 + u] = g_y[ybase + (size_t)u*COUTC*TDIM + tid];
    }
    __syncthreads();
    size_t ob = ((size_t)n*COUTC + o) * (size_t)JD;
    for (int idx = tid; idx < JD; idx += 256) {
        int t = idx / VV, u = idx - VV*t;
        out[ob + idx] = sy[t*27 + u];
    }
}

// ---------------- launch ----------------
extern "C" void kernel_launch(void* const* d_in, const int* in_sizes, int n_in,
                              void* d_out, int out_size) {
    const float* x     = (const float*)d_in[0];
    const float* A     = (const float*)d_in[1];
    const float* w2    = (const float*)d_in[4];
    const float* b2    = (const float*)d_in[5];
    const float* w3    = (const float*)d_in[6];
    const float* b3    = (const float*)d_in[7];
    const float* w4    = (const float*)d_in[8];
    const float* b4    = (const float*)d_in[9];
    const float* bn1_g = (const float*)d_in[10];
    const float* bn1_b = (const float*)d_in[11];
    const float* bn1_m = (const float*)d_in[12];
    const float* bn1_v = (const float*)d_in[13];
    const float* wt    = (const float*)d_in[14];
    const float* bt    = (const float*)d_in[15];
    const float* bn2_g = (const float*)d_in[16];
    const float* bn2_b = (const float*)d_in[17];
    const float* bn2_m = (const float*)d_in[18];
    const float* bn2_v = (const float*)d_in[19];
    const float* wr    = (const float*)d_in[20];
    const float* br    = (const float*)d_in[21];
    const float* bnr_g = (const float*)d_in[22];
    const float* bnr_b = (const float*)d_in[23];
    const float* bnr_m = (const float*)d_in[24];
    const float* bnr_v = (const float*)d_in[25];
    float* out = (float*)d_out;

    k_fold<<<(COUTC*COUTC*9 + 255)/256, 256>>>(w3, b3, w4, b4,
                                               bn1_g, bn1_b, bn1_m, bn1_v,
                                               wt, bt, bn2_g, bn2_b, bn2_m, bn2_v,
                                               wr, br, bnr_g, bnr_b, bnr_m, bnr_v);
    k_xT<<<NB*CINC, 256>>>(x);
    k_p<<<NB*ICC, 32>>>(w2, b2);
    k_zgemm<<<dim3(50, 3, NB), 256>>>();
    k_amix<<<NB*COUTC, 256>>>(A);
    k_mma<<<dim3(2, VV, NB), 256>>>();
    k_out<<<NB*COUTC, 256>>>(out);
}

// round 15
// speedup vs baseline: 1.2821x; 1.0336x over previous
#include <cuda_runtime.h>
#include <cstdint>

#define NB   32
#define CINC 64
#define COUTC 128
#define TDIM 256
#define VV   25
#define ICC  32
#define EPSB 1e-5f
#define JD   6400            // t*v columns per (n, channel)

// ---------------- scratch (device globals, no allocation) ----------------
__device__ float g_xT[(size_t)NB*CINC*VV*TDIM];     // tf32 x, [n][c][v][t]
__device__ float g_z[(size_t)NB*256*VV*TDIM];       // z3(0..127), z4(128..255): [n][o'][v][t]
__device__ float g_rT[(size_t)NB*VV*COUTC*TDIM];    // residual + consts, [n][v][o][t]
__device__ float g_hTp[(size_t)NB*VV*COUTC*264];    // padded h rows: [n][u][o][(4+256+4)]
__device__ float g_y[(size_t)NB*VV*COUTC*TDIM];     // final (y+r, relu), [n][u][o][t]
__device__ float g_xbar[NB*CINC*VV];
__device__ float g_p[NB*ICC*VV];
__device__ float g_wstk[384*CINC];                  // [w3*s1; w4*s1; wr*sr], tf32
__device__ float g_b3f[COUTC];
__device__ float g_b4f[COUTC];
__device__ float g_h1[COUTC];
__device__ float g_Cc[COUTC];
__device__ float g_wt2T[1152*COUTC];                // wt*s2 transposed [kk][o], tf32

// ---------------- helpers ----------------
__device__ __forceinline__ float to_tf32(float x) {
    uint32_t r;
    asm("cvt.rna.tf32.f32 %0, %1;" : "=r"(r) : "f"(x));
    return __uint_as_float(r);
}
__device__ __forceinline__ uint32_t smem_u32(const void* p) {
    uint32_t a;
    asm("{ .reg .u64 t; cvta.to.shared.u64 t, %1; cvt.u32.u64 %0, t; }" : "=r"(a) : "l"(p));
    return a;
}

// ---------------- K0: BN folding + weight stack + wt transpose ----------------
__global__ void k_fold(const float* __restrict__ w3, const float* __restrict__ b3,
                       const float* __restrict__ w4, const float* __restrict__ b4,
                       const float* __restrict__ bn1_g, const float* __restrict__ bn1_b,
                       const float* __restrict__ bn1_m, const float* __restrict__ bn1_v,
                       const float* __restrict__ wt,  const float* __restrict__ bt,
                       const float* __restrict__ bn2_g, const float* __restrict__ bn2_b,
                       const float* __restrict__ bn2_m, const float* __restrict__ bn2_v,
                       const float* __restrict__ wr,  const float* __restrict__ br,
                       const float* __restrict__ bnr_g, const float* __restrict__ bnr_b,
                       const float* __restrict__ bnr_m, const float* __restrict__ bnr_v) {
    int idx = blockIdx.x * blockDim.x + threadIdx.x;
    if (idx < COUTC*COUTC*9) {
        int o = idx / 1152, kk = idx - o*1152;
        float s2 = bn2_g[o] * rsqrtf(bn2_v[o] + EPSB);
        g_wt2T[kk*COUTC + o] = to_tf32(wt[idx] * s2);
    }
    if (idx < 384*CINC) {
        int op = idx >> 6, c = idx & 63;
        float w, s;
        if (op < 128) {
            s = bn1_g[op] * rsqrtf(bn1_v[op] + EPSB);
            w = w3[op*CINC + c];
        } else if (op < 256) {
            int o = op - 128;
            s = bn1_g[o] * rsqrtf(bn1_v[o] + EPSB);
            w = w4[o*CINC + c];
        } else {
            int o = op - 256;
            s = bnr_g[o] * rsqrtf(bnr_v[o] + EPSB);
            w = wr[o*CINC + c];
        }
        g_wstk[idx] = to_tf32(w * s);
    }
    if (idx < COUTC) {
        int o = idx;
        float s1 = bn1_g[o] * rsqrtf(bn1_v[o] + EPSB);
        float s2 = bn2_g[o] * rsqrtf(bn2_v[o] + EPSB);
        float sr = bnr_g[o] * rsqrtf(bnr_v[o] + EPSB);
        float h1 = bn1_b[o] - bn1_m[o]*s1;
        float h2 = bn2_b[o] - bn2_m[o]*s2;
        float hr = bnr_b[o] - bnr_m[o]*sr;
        g_b3f[o] = b3[o]*s1;
        g_b4f[o] = b4[o]*s1;
        g_h1[o]  = h1;
        g_Cc[o]  = br[o]*sr + hr + bt[o]*s2 + h2;
    }
}

// ---------------- K0.5: transpose x -> g_xT [n][c][v][t] (tf32) + fused xbar ----------
__global__ void __launch_bounds__(256) k_xT(const float* __restrict__ x) {
    int blk = blockIdx.x;                 // n*64 + c
    __shared__ float s[VV * 257];
    const float* src = x + (size_t)blk * JD;
    int tid = threadIdx.x;
    for (int idx = tid; idx < JD; idx += 256) {
        int t = idx / VV, v = idx - VV*t;
        s[v*257 + t] = src[idx];
    }
    __syncthreads();
    float* dst = g_xT + (size_t)blk * (VV*TDIM);
    #pragma unroll
    for (int v = 0; v < VV; v++) {
        dst[v*TDIM + tid] = to_tf32(s[v*257 + tid]);
    }
    // fused xbar: per-v mean over t (8 lanes per v, shfl reduce)
    {
        int v = tid >> 3, part = tid & 7;
        float sum = 0.f;
        if (v < VV) {
            for (int t = part; t < TDIM; t += 8) sum += s[v*257 + t];
        }
        sum += __shfl_xor_sync(0xffffffffu, sum, 1);
        sum += __shfl_xor_sync(0xffffffffu, sum, 2);
        sum += __shfl_xor_sync(0xffffffffu, sum, 4);
        if (v < VV && part == 0) g_xbar[blk*VV + v] = sum * (1.f / TDIM);
    }
}

// ---------------- K2: p = softmax_v(-(w2.xbar + b2)) ----------------
__global__ void k_p(const float* __restrict__ w2, const float* __restrict__ b2) {
    int blk = blockIdx.x;
    int n = blk / ICC, i = blk % ICC;
    int v = threadIdx.x;
    float val = -1e30f;
    if (v < VV) {
        float acc = b2[i];
        const float* xb = g_xbar + n*CINC*VV;
        #pragma unroll 8
        for (int c = 0; c < CINC; c++) acc += w2[i*CINC + c] * xb[c*VV + v];
        val = -acc;
    }
    float m = val;
    #pragma unroll
    for (int s = 16; s; s >>= 1) m = fmaxf(m, __shfl_xor_sync(0xffffffffu, m, s));
    float e = (v < VV) ? expf(val - m) : 0.f;
    float ssum = e;
    #pragma unroll
    for (int s = 16; s; s >>= 1) ssum += __shfl_xor_sync(0xffffffffu, ssum, s);
    if (v < VV) g_p[blk*VV + v] = e / ssum;
}

// ---------------- K3: Z = Wstack(384x64) @ xT(64 x [v][t]) per n, tf32 mma ----------
#define ZPA 68     // [o][k]: banks 4g+tg distinct
#define ZPB 136    // [k][t]: banks 8tg+g distinct

__global__ void __launch_bounds__(256, 2) k_zgemm() {
    __shared__ float sA[128*ZPA];
    __shared__ float sB[64*ZPB];
    __shared__ float ccs[COUTC];
    int tid = threadIdx.x, wid = tid >> 5, lane = tid & 31;
    int g = lane >> 2, tg = lane & 3;
    int warp_m = wid & 3, warp_n = wid >> 2;
    int jb = blockIdx.x;                 // 0..49
    int v  = jb >> 1, t0 = (jb & 1) * 128;
    int mg = blockIdx.y;                 // 0:z3 1:z4 2:zr
    int m0 = mg * 128;
    int n  = blockIdx.z;

    #pragma unroll
    for (int e = 0; e < 8; e++) {
        int i4 = e*256 + tid;
        int o = i4 >> 4, k4 = (i4 & 15) * 4;
        *(float4*)&sA[o*ZPA + k4] = *(const float4*)&g_wstk[(m0 + o)*CINC + k4];
    }
    #pragma unroll
    for (int e = 0; e < 8; e++) {
        int i4 = e*256 + tid;
        int c = i4 >> 5, t4 = (i4 & 31) * 4;
        *(float4*)&sB[c*ZPB + t4] =
            *(const float4*)&g_xT[(((size_t)n*CINC + c)*VV + v)*TDIM + t0 + t4];
    }
    if (mg == 2 && tid < COUTC) ccs[tid] = g_Cc[tid];
    __syncthreads();

    float acc[2][8][4];
    #pragma unroll
    for (int mt = 0; mt < 2; mt++)
        #pragma unroll
        for (int nt = 0; nt < 8; nt++)
            #pragma unroll
            for (int q = 0; q < 4; q++) acc[mt][nt][q] = 0.f;

    #pragma unroll
    for (int ks = 0; ks < 8; ks++) {
        int k0 = ks*8;
        uint32_t a[2][4];
        #pragma unroll
        for (int mt = 0; mt < 2; mt++) {
            int ob = warp_m*32 + mt*16;
            a[mt][0] = __float_as_uint(sA[(ob + g    )*ZPA + k0 + tg    ]);
            a[mt][1] = __float_as_uint(sA[(ob + g + 8)*ZPA + k0 + tg    ]);
            a[mt][2] = __float_as_uint(sA[(ob + g    )*ZPA + k0 + tg + 4]);
            a[mt][3] = __float_as_uint(sA[(ob + g + 8)*ZPA + k0 + tg + 4]);
        }
        #pragma unroll
        for (int nt = 0; nt < 8; nt++) {
            int tb = warp_n*64 + nt*8;
            uint32_t b0 = __float_as_uint(sB[(k0 + tg    )*ZPB + tb + g]);
            uint32_t b1 = __float_as_uint(sB[(k0 + tg + 4)*ZPB + tb + g]);
            #pragma unroll
            for (int mt = 0; mt < 2; mt++) {
                asm volatile(
                    "mma.sync.aligned.m16n8k8.row.col.f32.tf32.tf32.f32 "
                    "{%0,%1,%2,%3}, {%4,%5,%6,%7}, {%8,%9}, {%0,%1,%2,%3};"
                    : "+f"(acc[mt][nt][0]), "+f"(acc[mt][nt][1]),
                      "+f"(acc[mt][nt][2]), "+f"(acc[mt][nt][3])
                    : "r"(a[mt][0]), "r"(a[mt][1]), "r"(a[mt][2]), "r"(a[mt][3]),
                      "r"(b0), "r"(b1));
            }
        }
    }

    if (mg < 2) {
        size_t zb = (size_t)n*(256*JD) + (size_t)m0*JD + (size_t)v*TDIM + t0;
        #pragma unroll
        for (int mt = 0; mt < 2; mt++) {
            int ob = warp_m*32 + mt*16;
            #pragma unroll
            for (int nt = 0; nt < 8; nt++) {
                int tl = warp_n*64 + nt*8 + 2*tg;
                *(float2*)&g_z[zb + (size_t)(ob + g    )*JD + tl] =
                    make_float2(acc[mt][nt][0], acc[mt][nt][1]);
                *(float2*)&g_z[zb + (size_t)(ob + g + 8)*JD + tl] =
                    make_float2(acc[mt][nt][2], acc[mt][nt][3]);
            }
        }
    } else {
        size_t rb = (((size_t)n*VV + v)*COUTC)*TDIM + t0;
        #pragma unroll
        for (int mt = 0; mt < 2; mt++) {
            int ob = warp_m*32 + mt*16;
            #pragma unroll
            for (int nt = 0; nt < 8; nt++) {
                int tl = warp_n*64 + nt*8 + 2*tg;
                float c0 = ccs[ob + g], c1 = ccs[ob + g + 8];
                *(float2*)&g_rT[rb + (size_t)(ob + g    )*TDIM + tl] =
                    make_float2(acc[mt][nt][0] + c0, acc[mt][nt][1] + c0);
                *(float2*)&g_rT[rb + (size_t)(ob + g + 8)*TDIM + tl] =
                    make_float2(acc[mt][nt][2] + c1, acc[mt][nt][3] + c1);
            }
        }
    }
}

// ---------------- K3.5: A-mix as tf32 mma + p-dot base + BN1/ReLU -> g_hTp ----------
// Per block (n,o): Y[u=25(pad32), t=256] = A[25x25(pad32)] @ (z4[25x256]+b4)
// base[t] = b3f+h1 + sum_v p[v]*z3[v][t]; h = tf32(relu(Y + base)).
#define APA 36     // sA [u][v] pitch: A-frag banks (4g+tg)%32 distinct
#define APB 264    // sB [v][t] pitch: B-frag banks (8tg+g)%32 distinct (264%32==8)

__global__ void __launch_bounds__(256) k_amix(const float* __restrict__ A) {
    int blk = blockIdx.x;                 // n*128 + o
    int n = blk >> 7, o = blk & 127;
    __shared__ float sA[32*APA];          // 1152
    __shared__ float sB[32*APB];          // 8448 (rows 25..31 garbage; A cols zero)
    __shared__ float sbase[TDIM];
    __shared__ float ps[VV];
    int tid = threadIdx.x, wid = tid >> 5, lane = tid & 31;
    int g = lane >> 2, tg = lane & 3;
    int warp_m = wid & 1, warp_n = wid >> 1;   // u-half, t-quarter

    // pass 1: zero sA (pads), load p
    for (int idx = tid; idx < 32*APA; idx += 256) sA[idx] = 0.f;
    if (tid < VV) ps[tid] = g_p[(n*ICC + (o & 31))*VV + tid];
    __syncthreads();

    // pass 2: A (tf32), z4+b4 (tf32), base
    for (int idx = tid; idx < VV*VV; idx += 256) {
        int u = idx / VV, v = idx - u*VV;
        sA[u*APA + v] = to_tf32(A[idx]);
    }
    const float* z3p = g_z + (size_t)n*(256*JD) + (size_t)o*JD;
    const float* z4p = z3p + (size_t)128*JD;
    float b4 = g_b4f[o];
    #pragma unroll
    for (int v = 0; v < VV; v++) {
        sB[v*APB + tid] = to_tf32(z4p[v*TDIM + tid] + b4);
    }
    {
        float base = g_b3f[o] + g_h1[o];
        #pragma unroll
        for (int v = 0; v < VV; v++) base += ps[v] * z3p[v*TDIM + tid];
        sbase[tid] = base;
    }
    __syncthreads();

    // GEMM: M=32, N=256, K=32
    float acc[8][4];
    #pragma unroll
    for (int nt = 0; nt < 8; nt++)
        #pragma unroll
        for (int q = 0; q < 4; q++) acc[nt][q] = 0.f;

    int ub = warp_m*16;
    #pragma unroll
    for (int ks = 0; ks < 4; ks++) {
        int k0 = ks*8;
        uint32_t a0 = __float_as_uint(sA[(ub + g    )*APA + k0 + tg    ]);
        uint32_t a1 = __float_as_uint(sA[(ub + g + 8)*APA + k0 + tg    ]);
        uint32_t a2 = __float_as_uint(sA[(ub + g    )*APA + k0 + tg + 4]);
        uint32_t a3 = __float_as_uint(sA[(ub + g + 8)*APA + k0 + tg + 4]);
        #pragma unroll
        for (int nt = 0; nt < 8; nt++) {
            int tb = warp_n*64 + nt*8;
            uint32_t b0 = __float_as_uint(sB[(k0 + tg    )*APB + tb + g]);
            uint32_t b1 = __float_as_uint(sB[(k0 + tg + 4)*APB + tb + g]);
            asm volatile(
                "mma.sync.aligned.m16n8k8.row.col.f32.tf32.tf32.f32 "
                "{%0,%1,%2,%3}, {%4,%5,%6,%7}, {%8,%9}, {%0,%1,%2,%3};"
                : "+f"(acc[nt][0]), "+f"(acc[nt][1]),
                  "+f"(acc[nt][2]), "+f"(acc[nt][3])
                : "r"(a0), "r"(a1), "r"(a2), "r"(a3), "r"(b0), "r"(b1));
        }
    }

    // epilogue: +base, ReLU, tf32 round, float2 stores (full 32B sectors)
    size_t hb = ((size_t)(n*VV)*COUTC + o)*264;
    int u0 = ub + g, u1 = ub + g + 8;
    #pragma unroll
    for (int nt = 0; nt < 8; nt++) {
        int t = warp_n*64 + nt*8 + 2*tg;
        float bs0 = sbase[t], bs1 = sbase[t + 1];
        if (u0 < VV) {
            size_t row = hb + (size_t)u0*(COUTC*264);
            float2 hv = make_float2(to_tf32(fmaxf(acc[nt][0] + bs0, 0.f)),
                                    to_tf32(fmaxf(acc[nt][1] + bs1, 0.f)));
            *(float2*)&g_hTp[row + 4 + t] = hv;
        }
        if (u1 < VV) {
            size_t row = hb + (size_t)u1*(COUTC*264);
            float2 hv = make_float2(to_tf32(fmaxf(acc[nt][2] + bs0, 0.f)),
                                    to_tf32(fmaxf(acc[nt][3] + bs1, 0.f)));
            *(float2*)&g_hTp[row + 4 + t] = hv;
        }
    }
    // halo pads
    for (int idx = tid; idx < VV*8; idx += 256) {
        int u = idx >> 3, j = idx & 7;
        size_t row = hb + (size_t)u*(COUTC*264);
        g_hTp[row + (j < 4 ? j : 256 + j)] = 0.f;
    }
}

// ---------------- K4: temporal conv GEMM, KC=8, 4-stage A + 6-row H ring ----------
#define NCH 144
#define MPA 136        // A [j][o] pitch: banks 8tg+g distinct
#define ASTG (8*MPA)   // 1088 floats per A stage
#define SH_OFF (4*ASTG)  // 4352
#define SHP 264        // ring row pitch (136 used)
#define SMEM_FL (COUTC*68)  // 8704: epilogue stage dominates

__global__ void __launch_bounds__(256, 2) k_mma() {
    __shared__ float sm[SMEM_FL];
    int tid = threadIdx.x, wid = tid >> 5, lane = tid & 31;
    int g = lane >> 2, tg = lane & 3;
    int warp_m = wid & 3, warp_n = wid >> 2;
    int t0 = blockIdx.x * 128;
    int u  = blockIdx.y;
    int n  = blockIdx.z;
    uint32_t sb = smem_u32(sm);
    const float* hrow = g_hTp + ((size_t)(n*VV + u)*COUTC)*264;   // + i*264 (+t0)

    float acc[2][8][4];
    #pragma unroll
    for (int mt = 0; mt < 2; mt++)
        #pragma unroll
        for (int nt = 0; nt < 8; nt++)
            #pragma unroll
            for (int q = 0; q < 4; q++) acc[mt][nt][q] = 0.f;

    int next_row = 0;
    auto issue = [&](int c) {
        {   // A chunk c -> stage c&3 : one 16B cp.async per thread
            int j = tid >> 5, o4 = (tid & 31) * 4;
            uint32_t dst = sb + (((c & 3)*ASTG) + j*MPA + o4) * 4;
            const float* src = g_wt2T + (size_t)(c*8 + j)*COUTC + o4;
            asm volatile("cp.async.ca.shared.global [%0], [%1], 16;" :: "r"(dst), "l"(src));
        }
        int imax = (8*c + 7) / 9;
        while (next_row <= imax) {
            if (tid < 34) {
                int slot = next_row % 6;
                uint32_t dst = sb + (SH_OFF + slot*SHP + tid*4) * 4;
                const float* src = hrow + (size_t)next_row*264 + t0 + tid*4;
                asm volatile("cp.async.ca.shared.global [%0], [%1], 16;" :: "r"(dst), "l"(src));
            }
            next_row++;
        }
        asm volatile("cp.async.commit_group;" ::: "memory");
    };

    issue(0); issue(1); issue(2);
    for (int c = 0; c < NCH; c++) {
        asm volatile("cp.async.wait_group 2;" ::: "memory");
        __syncthreads();
        if (c + 3 < NCH) issue(c + 3);
        else asm volatile("cp.async.commit_group;" ::: "memory");

        const float* sA = sm + (c & 3)*ASTG;
        uint32_t a[2][4];
        #pragma unroll
        for (int mt = 0; mt < 2; mt++) {
            int ob = warp_m*32 + mt*16;
            a[mt][0] = __float_as_uint(sA[ tg     *MPA + ob + g    ]);
            a[mt][1] = __float_as_uint(sA[ tg     *MPA + ob + g + 8]);
            a[mt][2] = __float_as_uint(sA[(tg + 4)*MPA + ob + g    ]);
            a[mt][3] = __float_as_uint(sA[(tg + 4)*MPA + ob + g + 8]);
        }
        int kb0 = c*8 + tg, kb1 = kb0 + 4;
        int i0 = (kb0 * 7282) >> 16; int k0 = kb0 - 9*i0;
        int i1 = (kb1 * 7282) >> 16; int k1 = kb1 - 9*i1;
        const float* h0 = sm + SH_OFF + (i0 % 6)*SHP + k0 + g;
        const float* h1 = sm + SH_OFF + (i1 % 6)*SHP + k1 + g;
        #pragma unroll
        for (int nt = 0; nt < 8; nt++) {
            int tb = warp_n*64 + nt*8;
            uint32_t b0 = __float_as_uint(h0[tb]);
            uint32_t b1 = __float_as_uint(h1[tb]);
            #pragma unroll
            for (int mt = 0; mt < 2; mt++) {
                asm volatile(
                    "mma.sync.aligned.m16n8k8.row.col.f32.tf32.tf32.f32 "
                    "{%0,%1,%2,%3}, {%4,%5,%6,%7}, {%8,%9}, {%0,%1,%2,%3};"
                    : "+f"(acc[mt][nt][0]), "+f"(acc[mt][nt][1]),
                      "+f"(acc[mt][nt][2]), "+f"(acc[mt][nt][3])
                    : "r"(a[mt][0]), "r"(a[mt][1]), "r"(a[mt][2]), "r"(a[mt][3]),
                      "r"(b0), "r"(b1));
            }
        }
    }

    // Epilogue: acc -> stage -> (+rT, ReLU) -> g_y, float4
    float* stage = sm;
    size_t yb = (((size_t)n*VV + u)*COUTC)*TDIM + t0;
    #pragma unroll
    for (int rr = 0; rr < 2; rr++) {
        __syncthreads();
        if (warp_n == rr) {
            #pragma unroll
            for (int mt = 0; mt < 2; mt++) {
                int o = warp_m*32 + mt*16 + g;
                #pragma unroll
                for (int nt = 0; nt < 8; nt++) {
                    int tl = nt*8 + 2*tg;
                    stage[ o     *68 + tl    ] = acc[mt][nt][0];
                    stage[ o     *68 + tl + 1] = acc[mt][nt][1];
                    stage[(o + 8)*68 + tl    ] = acc[mt][nt][2];
                    stage[(o + 8)*68 + tl + 1] = acc[mt][nt][3];
                }
            }
        }
        __syncthreads();
        #pragma unroll
        for (int e = 0; e < 8; e++) {
            int i4 = e*256 + tid;            // 2048 float4 = 128 o x 64 t
            int o = i4 >> 4, tl = (i4 & 15) * 4;
            size_t gi = yb + (size_t)o*TDIM + rr*64 + tl;
            float4 sv = *(float4*)&stage[o*68 + tl];
            float4 rv = *(const float4*)&g_rT[gi];
            sv.x = fmaxf(sv.x + rv.x, 0.f);
            sv.y = fmaxf(sv.y + rv.y, 0.f);
            sv.z = fmaxf(sv.z + rv.z, 0.f);
            sv.w = fmaxf(sv.w + rv.w, 0.f);
            *(float4*)&g_y[gi] = sv;
        }
    }
}

// ---------------- K5: pure transpose g_y -> out [n][o][t][u] ----------------
__global__ void __launch_bounds__(256) k_out(float* __restrict__ out) {
    int blk = blockIdx.x;                  // n*128 + o
    int n = blk >> 7, o = blk & 127;
    __shared__ float sy[TDIM * 27];
    int tid = threadIdx.x;
    size_t ybase = (((size_t)n*VV)*COUTC + o)*TDIM;
    #pragma unroll
    for (int u = 0; u < VV; u++) {
        sy[tid*27 + u] = g_y[ybase + (size_t)u*COUTC*TDIM + tid];
    }
    __syncthreads();
    size_t ob = ((size_t)n*COUTC + o) * (size_t)JD;
    for (int idx = tid; idx < JD; idx += 256) {
        int t = idx / VV, u = idx - VV*t;
        out[ob + idx] = sy[t*27 + u];
    }
}

// ---------------- launch ----------------
extern "C" void kernel_launch(void* const* d_in, const int* in_sizes, int n_in,
                              void* d_out, int out_size) {
    const float* x     = (const float*)d_in[0];
    const float* A     = (const float*)d_in[1];
    const float* w2    = (const float*)d_in[4];
    const float* b2    = (const float*)d_in[5];
    const float* w3    = (const float*)d_in[6];
    const float* b3    = (const float*)d_in[7];
    const float* w4    = (const float*)d_in[8];
    const float* b4    = (const float*)d_in[9];
    const float* bn1_g = (const float*)d_in[10];
    const float* bn1_b = (const float*)d_in[11];
    const float* bn1_m = (const float*)d_in[12];
    const float* bn1_v = (const float*)d_in[13];
    const float* wt    = (const float*)d_in[14];
    const float* bt    = (const float*)d_in[15];
    const float* bn2_g = (const float*)d_in[16];
    const float* bn2_b = (const float*)d_in[17];
    const float* bn2_m = (const float*)d_in[18];
    const float* bn2_v = (const float*)d_in[19];
    const float* wr    = (const float*)d_in[20];
    const float* br    = (const float*)d_in[21];
    const float* bnr_g = (const float*)d_in[22];
    const float* bnr_b = (const float*)d_in[23];
    const float* bnr_m = (const float*)d_in[24];
    const float* bnr_v = (const float*)d_in[25];
    float* out = (float*)d_out;

    k_fold<<<(COUTC*COUTC*9 + 255)/256, 256>>>(w3, b3, w4, b4,
                                               bn1_g, bn1_b, bn1_m, bn1_v,
                                               wt, bt, bn2_g, bn2_b, bn2_m, bn2_v,
                                               wr, br, bnr_g, bnr_b, bnr_m, bnr_v);
    k_xT<<<NB*CINC, 256>>>(x);
    k_p<<<NB*ICC, 32>>>(w2, b2);
    k_zgemm<<<dim3(50, 3, NB), 256>>>();
    k_amix<<<NB*COUTC, 256>>>(A);
    k_mma<<<dim3(2, VV, NB), 256>>>();
    k_out<<<NB*COUTC, 256>>>(out);
}